// round 2
// baseline (speedup 1.0000x reference)
#include <cuda_runtime.h>
#include <math.h>

#define T_TOK 2048
#define DD    1024
#define HH    1024
#define SS    20480
#define KPRUNE 819

// ---------------- scratch (device globals; no allocation allowed) ----------------
__device__ float g_h1[T_TOK * DD];
__device__ float g_h2[T_TOK * DD];
__device__ float g_wtd[T_TOK * DD];
__device__ float g_prefix[(T_TOK + 1) * DD];
__device__ float g_csum[16 * DD];
__device__ float g_Pa[T_TOK * DD];
__device__ float g_Pb[T_TOK * DD];
__device__ float g_Q[(T_TOK + 1) * DD];
__device__ float g_s1[(size_t)SS * HH];
__device__ float g_s2[(size_t)SS * HH];
__device__ float g_zbias[DD];   // zero-initialized

// ---------------- fp32 SGEMM: C = act(A[MxK] @ B[KxN] + bias) ----------------
// BM=BN=128, BK=8, 256 threads, 8x8 per-thread microtile.
template <int RELU>
__global__ __launch_bounds__(256, 2)
void sgemm_kernel(const float* __restrict__ A, const float* __restrict__ B,
                  const float* __restrict__ bias, float* __restrict__ C,
                  int M, int K, int N) {
    __shared__ float As[8][128];
    __shared__ float Bs[8][128];
    const int tid = threadIdx.x;
    const int bm = blockIdx.y * 128;
    const int bn = blockIdx.x * 128;
    const int tx = tid & 15;        // 0..15 (col group)
    const int ty = tid >> 4;        // 0..15 (row group)
    const int aRow = tid >> 1;          // 0..127
    const int aCol = (tid & 1) * 4;     // 0 or 4
    const int bRow = tid >> 5;          // 0..7
    const int bCol = (tid & 31) * 4;    // 0..124

    float acc[8][8];
#pragma unroll
    for (int i = 0; i < 8; i++)
#pragma unroll
        for (int j = 0; j < 8; j++) acc[i][j] = 0.f;

    for (int k0 = 0; k0 < K; k0 += 8) {
        float4 av = make_float4(0.f, 0.f, 0.f, 0.f);
        if (bm + aRow < M)
            av = *(const float4*)&A[(size_t)(bm + aRow) * K + k0 + aCol];
        As[aCol + 0][aRow] = av.x;
        As[aCol + 1][aRow] = av.y;
        As[aCol + 2][aRow] = av.z;
        As[aCol + 3][aRow] = av.w;
        *(float4*)&Bs[bRow][bCol] = *(const float4*)&B[(size_t)(k0 + bRow) * N + bn + bCol];
        __syncthreads();
#pragma unroll
        for (int k = 0; k < 8; k++) {
            float a[8], b[8];
            *(float4*)(a)     = *(float4*)&As[k][ty * 8];
            *(float4*)(a + 4) = *(float4*)&As[k][ty * 8 + 4];
            *(float4*)(b)     = *(float4*)&Bs[k][tx * 8];
            *(float4*)(b + 4) = *(float4*)&Bs[k][tx * 8 + 4];
#pragma unroll
            for (int i = 0; i < 8; i++)
#pragma unroll
                for (int j = 0; j < 8; j++) acc[i][j] += a[i] * b[j];
        }
        __syncthreads();
    }

#pragma unroll
    for (int i = 0; i < 8; i++) {
        int row = bm + ty * 8 + i;
        if (row < M) {
#pragma unroll
            for (int j = 0; j < 8; j++) {
                float v = acc[i][j] + bias[bn + tx * 8 + j];
                if (RELU) v = fmaxf(v, 0.f);
                acc[i][j] = v;
            }
            *(float4*)&C[(size_t)row * N + bn + tx * 8]     = *(float4*)&acc[i][0];
            *(float4*)&C[(size_t)row * N + bn + tx * 8 + 4] = *(float4*)&acc[i][4];
        }
    }
}

// ---------------- softmax over feature dim, times embeds ----------------
__global__ void softmax_mul_kernel(const float* __restrict__ alpha,
                                   const float* __restrict__ emb,
                                   float* __restrict__ wtd) {
    const int r = blockIdx.x;
    const int tid = threadIdx.x;  // 256
    __shared__ float red[256];
    const float4* a4 = (const float4*)(alpha + (size_t)r * DD);
    float4 a = a4[tid];
    float m = fmaxf(fmaxf(a.x, a.y), fmaxf(a.z, a.w));
    red[tid] = m;
    __syncthreads();
    for (int s = 128; s > 0; s >>= 1) {
        if (tid < s) red[tid] = fmaxf(red[tid], red[tid + s]);
        __syncthreads();
    }
    const float mx = red[0];
    __syncthreads();
    float4 e;
    e.x = expf(a.x - mx); e.y = expf(a.y - mx);
    e.z = expf(a.z - mx); e.w = expf(a.w - mx);
    red[tid] = e.x + e.y + e.z + e.w;
    __syncthreads();
    for (int s = 128; s > 0; s >>= 1) {
        if (tid < s) red[tid] += red[tid + s];
        __syncthreads();
    }
    const float inv = 1.f / red[0];
    float4 em = ((const float4*)(emb + (size_t)r * DD))[tid];
    float4 o;
    o.x = e.x * inv * em.x; o.y = e.y * inv * em.y;
    o.z = e.z * inv * em.z; o.w = e.w * inv * em.w;
    ((float4*)(wtd + (size_t)r * DD))[tid] = o;
}

// ---------------- column-wise prefix sum (3 passes) ----------------
__global__ void scan_chunks_kernel(const float* __restrict__ wtd, float* __restrict__ csum) {
    const int c = blockIdx.x;                       // 0..15
    const int col = blockIdx.y * 128 + threadIdx.x; // 0..1023
    float s = 0.f;
#pragma unroll 8
    for (int r = 0; r < 128; r++) s += wtd[(size_t)(c * 128 + r) * DD + col];
    csum[c * DD + col] = s;
}

__global__ void scan_offsets_kernel(float* __restrict__ csum) {
    const int col = blockIdx.x * 256 + threadIdx.x; // 1024 total
    float run = 0.f;
#pragma unroll
    for (int c = 0; c < 16; c++) {
        float t = csum[c * DD + col];
        csum[c * DD + col] = run;
        run += t;
    }
}

__global__ void scan_write_kernel(const float* __restrict__ wtd, const float* __restrict__ csum,
                                  float* __restrict__ prefix) {
    const int c = blockIdx.x;
    const int col = blockIdx.y * 128 + threadIdx.x;
    float run = csum[c * DD + col];
    if (c == 0) prefix[col] = 0.f;
#pragma unroll 8
    for (int r = 0; r < 128; r++) {
        run += wtd[(size_t)(c * 128 + r) * DD + col];
        prefix[(size_t)(c * 128 + r + 1) * DD + col] = run;
    }
}

// ---------------- span assembly: g output + s1 pre-activation ----------------
__global__ void assemble_kernel(const float* __restrict__ L,
                                const int* __restrict__ starts,
                                const int* __restrict__ ends,
                                const float* __restrict__ bs1,
                                float* __restrict__ out_g,
                                float* __restrict__ s1) {
    const int i = blockIdx.x;      // span
    const int t = threadIdx.x;     // 0..255 (float4 index over 1024 features)
    const int s = starts[i];
    const int e = ends[i];
    const float4* L4  = (const float4*)L;
    const float4* pf4 = (const float4*)g_prefix;
    const float4* Pa4 = (const float4*)g_Pa;
    const float4* Pb4 = (const float4*)g_Pb;
    const float4* Q4  = (const float4*)g_Q;

    float4 ls = L4[(size_t)s * 256 + t];
    float4 le = L4[(size_t)e * 256 + t];
    float4 pe = pf4[(size_t)(e + 1) * 256 + t];
    float4 ps = pf4[(size_t)s * 256 + t];
    float4 xa = make_float4(pe.x - ps.x, pe.y - ps.y, pe.z - ps.z, pe.w - ps.w);

    float4* go = (float4*)(out_g + (size_t)i * 3072);
    go[t]       = ls;
    go[256 + t] = le;
    go[512 + t] = xa;

    float4 pa = Pa4[(size_t)s * 256 + t];
    float4 pb = Pb4[(size_t)e * 256 + t];
    float4 qe = Q4[(size_t)(e + 1) * 256 + t];
    float4 qs = Q4[(size_t)s * 256 + t];
    float4 bb = ((const float4*)bs1)[t];
    float4 v;
    v.x = fmaxf(pa.x + pb.x + qe.x - qs.x + bb.x, 0.f);
    v.y = fmaxf(pa.y + pb.y + qe.y - qs.y + bb.y, 0.f);
    v.z = fmaxf(pa.z + pb.z + qe.z - qs.z + bb.z, 0.f);
    v.w = fmaxf(pa.w + pb.w + qe.w - qs.w + bb.w, 0.f);
    ((float4*)s1)[(size_t)i * 256 + t] = v;
}

// ---------------- scores = s2 @ Ws3 + bs3 (one warp per row) ----------------
__global__ void scores_kernel(const float* __restrict__ s2, const float* __restrict__ Ws3,
                              const float* __restrict__ bs3, float* __restrict__ out) {
    const int warp = (blockIdx.x * blockDim.x + threadIdx.x) >> 5;
    const int lane = threadIdx.x & 31;
    if (warp >= SS) return;
    const float4* r4 = (const float4*)(s2 + (size_t)warp * HH);
    const float4* w4 = (const float4*)Ws3;
    float sum = 0.f;
#pragma unroll
    for (int k = lane; k < 256; k += 32) {
        float4 a = r4[k];
        float4 w = w4[k];
        sum += a.x * w.x + a.y * w.y + a.z * w.z + a.w * w.w;
    }
#pragma unroll
    for (int o = 16; o; o >>= 1) sum += __shfl_xor_sync(0xFFFFFFFFu, sum, o);
    if (lane == 0) out[warp] = sum + bs3[0];
}

// ---------------- exact top-k by rank counting (matches jax.lax.top_k) ----------------
__global__ void topk_kernel(const float* __restrict__ scores, float* __restrict__ out_idx) {
    __shared__ float sh[4096];
    const int i = blockIdx.x * 256 + threadIdx.x;   // 80*256 = 20480
    const float my = scores[i];
    int rank = 0;
    for (int c = 0; c < SS; c += 4096) {
#pragma unroll
        for (int j = threadIdx.x; j < 4096; j += 256) sh[j] = scores[c + j];
        __syncthreads();
#pragma unroll 8
        for (int j = 0; j < 4096; j++) {
            float v = sh[j];
            rank += (v > my) ? 1 : ((v == my && (c + j) < i) ? 1 : 0);
        }
        __syncthreads();
    }
    if (rank < KPRUNE) out_idx[rank] = (float)i;
}

// ---------------- launch ----------------
static float* sym_addr(const void* symbol) {
    void* p = nullptr;
    cudaGetSymbolAddress(&p, symbol);
    return (float*)p;
}

extern "C" void kernel_launch(void* const* d_in, const int* in_sizes, int n_in,
                              void* d_out, int out_size) {
    const float* L    = (const float*)d_in[0];
    const float* emb  = (const float*)d_in[1];
    const float* Wa1  = (const float*)d_in[2];
    const float* ba1  = (const float*)d_in[3];
    const float* Wa2  = (const float*)d_in[4];
    const float* ba2  = (const float*)d_in[5];
    const float* Wa3  = (const float*)d_in[6];
    const float* ba3  = (const float*)d_in[7];
    const float* Ws1  = (const float*)d_in[8];
    const float* bs1  = (const float*)d_in[9];
    const float* Ws2  = (const float*)d_in[10];
    const float* bs2  = (const float*)d_in[11];
    const float* Ws3  = (const float*)d_in[12];
    const float* bs3  = (const float*)d_in[13];
    const int* starts = (const int*)d_in[14];
    const int* ends   = (const int*)d_in[15];

    float* out        = (float*)d_out;
    float* out_scores = out;
    float* out_g      = out + SS;
    float* out_idx    = out + SS + (size_t)SS * 3072;

    float* h1  = sym_addr(g_h1);
    float* h2  = sym_addr(g_h2);
    float* wtd = sym_addr(g_wtd);
    float* pfx = sym_addr(g_prefix);
    float* cs  = sym_addr(g_csum);
    float* Pa  = sym_addr(g_Pa);
    float* Pb  = sym_addr(g_Pb);
    float* Q   = sym_addr(g_Q);
    float* s1  = sym_addr(g_s1);
    float* s2  = sym_addr(g_s2);
    float* zb  = sym_addr(g_zbias);

    dim3 gT(DD / 128, T_TOK / 128);          // 8 x 16
    dim3 gQ(DD / 128, (T_TOK + 1 + 127) / 128); // 8 x 17
    dim3 gS2(HH / 128, SS / 128);            // 8 x 160

    // activate path
    sgemm_kernel<1><<<gT, 256>>>(L,  Wa1, ba1, h1, T_TOK, DD, DD);
    sgemm_kernel<1><<<gT, 256>>>(h1, Wa2, ba2, h2, T_TOK, DD, DD);
    sgemm_kernel<0><<<gT, 256>>>(h2, Wa3, ba3, h1, T_TOK, DD, DD);  // alpha -> h1
    softmax_mul_kernel<<<T_TOK, 256>>>(h1, emb, wtd);

    // prefix sums over tokens
    scan_chunks_kernel<<<dim3(16, 8), 128>>>(wtd, cs);
    scan_offsets_kernel<<<4, 256>>>(cs);
    scan_write_kernel<<<dim3(16, 8), 128>>>(wtd, cs, pfx);

    // collapsed first scoring layer: Pa/Pb/Q tables
    sgemm_kernel<0><<<gT, 256>>>(L,   Ws1,                 zb, Pa, T_TOK,     DD, HH);
    sgemm_kernel<0><<<gT, 256>>>(L,   Ws1 + (size_t)DD * HH,     zb, Pb, T_TOK,     DD, HH);
    sgemm_kernel<0><<<gQ, 256>>>(pfx, Ws1 + (size_t)2 * DD * HH, zb, Q,  T_TOK + 1, DD, HH);

    // g output + s1
    assemble_kernel<<<SS, 256>>>(L, starts, ends, bs1, out_g, s1);

    // second scoring layer (dominant GEMM)
    sgemm_kernel<1><<<gS2, 256>>>(s1, Ws2, bs2, s2, SS, HH, HH);

    // scores + exact top-k
    scores_kernel<<<SS / 8, 256>>>(s2, Ws3, bs3, out_scores);
    topk_kernel<<<SS / 256, 256>>>(out_scores, out_idx);
}

// round 5
// speedup vs baseline: 1.0092x; 1.0092x over previous
#include <cuda_runtime.h>
#include <cuda_bf16.h>
#include <math.h>
#include <stdint.h>

#define T_TOK 2048
#define DD    1024
#define SS    20480
#define KPRUNE 819
#define MPAD_Q 2176   // 2049 rows padded to 17*128

typedef __nv_bfloat16 bf16;
typedef __nv_bfloat162 bf162;

// ---------------- scratch (device globals; no allocation allowed) ----------------
__device__ __align__(16) bf16 g_Lh[T_TOK * DD], g_Lm[T_TOK * DD], g_Ll[T_TOK * DD];
__device__ __align__(16) bf16 g_Wh[7][DD * DD], g_Wm[7][DD * DD], g_Wl[7][DD * DD];
__device__ __align__(16) bf16 g_h1h[T_TOK * DD], g_h1m[T_TOK * DD], g_h1l[T_TOK * DD];
__device__ __align__(16) bf16 g_h2h[T_TOK * DD], g_h2m[T_TOK * DD], g_h2l[T_TOK * DD];
__device__ __align__(16) bf16 g_pfh[MPAD_Q * DD], g_pfm[MPAD_Q * DD], g_pfl[MPAD_Q * DD];
__device__ __align__(16) bf16 g_s1h[(size_t)SS * DD], g_s1m[(size_t)SS * DD], g_s1l[(size_t)SS * DD];
__device__ float g_PaPb[(size_t)T_TOK * 2048];   // [Pa | Pb]
__device__ float g_alpha[T_TOK * DD];
__device__ float g_wtd[T_TOK * DD];
__device__ float g_prefix[(T_TOK + 1) * DD];
__device__ float g_csum[16 * DD];
__device__ float g_Q[MPAD_Q * DD];
__device__ float g_zbias[2048];                  // zero-initialized
__device__ float g_spart[16][SS];
__device__ int   g_hist[65536];
__device__ int   g_cut[1];
__device__ int   g_ccount[1];
__device__ float g_cscore[SS];
__device__ int   g_cidx[SS];

// ---------------- helpers ----------------
__device__ __forceinline__ uint32_t smem_u32(const void* p) {
    uint32_t a;
    asm("{ .reg .u64 t; cvta.to.shared.u64 t, %1; cvt.u32.u64 %0, t; }" : "=r"(a) : "l"(p));
    return a;
}
__device__ __forceinline__ void bf16split3(float x, bf16& h, bf16& m, bf16& l) {
    h = __float2bfloat16_rn(x);
    float r1 = x - __bfloat162float(h);
    m = __float2bfloat16_rn(r1);
    float r2 = r1 - __bfloat162float(m);
    l = __float2bfloat16_rn(r2);
}

#define LDMX4(r, addr)                                                        \
    asm volatile("ldmatrix.sync.aligned.m8n8.x4.shared.b16 {%0,%1,%2,%3}, [%4];" \
        : "=r"((r)[0]), "=r"((r)[1]), "=r"((r)[2]), "=r"((r)[3]) : "r"(addr))

#define MMA16816(c, a, b0, b1)                                                \
    asm volatile("mma.sync.aligned.m16n8k16.row.col.f32.bf16.bf16.f32 "       \
        "{%0,%1,%2,%3},{%4,%5,%6,%7},{%8,%9},{%0,%1,%2,%3};"                  \
        : "+f"((c)[0]), "+f"((c)[1]), "+f"((c)[2]), "+f"((c)[3])              \
        : "r"((a)[0]), "r"((a)[1]), "r"((a)[2]), "r"((a)[3]), "r"(b0), "r"(b1))

#define CPASYNC16(dst, src)                                                   \
    asm volatile("cp.async.cg.shared.global [%0],[%1],16;" :: "r"(dst), "l"(src) : "memory")

// ---------------- one-shot prep kernels ----------------
__global__ void split3_kernel(const float* __restrict__ in,
                              bf16* __restrict__ oh, bf16* __restrict__ om,
                              bf16* __restrict__ ol, int n2) {
    int i = blockIdx.x * 256 + threadIdx.x;
    if (i >= n2) return;
    float2 v = ((const float2*)in)[i];
    bf16 hx, mx, lx, hy, my, ly;
    bf16split3(v.x, hx, mx, lx);
    bf16split3(v.y, hy, my, ly);
    ((bf162*)oh)[i] = bf162(hx, hy);
    ((bf162*)om)[i] = bf162(mx, my);
    ((bf162*)ol)[i] = bf162(lx, ly);
}

// out[N][K] planes = split3(in[K][N])
__global__ void transpose_split3_kernel(const float* __restrict__ in,
                                        bf16* __restrict__ oh, bf16* __restrict__ om,
                                        bf16* __restrict__ ol) {
    __shared__ float t[32][33];
    int bx = blockIdx.x * 32, by = blockIdx.y * 32;
#pragma unroll
    for (int i = 0; i < 32; i += 8)
        t[threadIdx.y + i][threadIdx.x] = in[(size_t)(by + threadIdx.y + i) * DD + bx + threadIdx.x];
    __syncthreads();
#pragma unroll
    for (int i = 0; i < 32; i += 8) {
        float v = t[threadIdx.x][threadIdx.y + i];
        bf16 h, m, l; bf16split3(v, h, m, l);
        size_t o = (size_t)(bx + threadIdx.y + i) * DD + by + threadIdx.x;
        oh[o] = h; om[o] = m; ol[o] = l;
    }
}

// ---------------- emulated-fp32 GEMM via 3xbf16 / 8-term mma.sync ----------------
// C[M x N] = A[M x 1024] @ B[N][1024]^T (+bias). CTA 128x256, 8 warps 64x64, BK=16.
// MODE 0: store fp32 C (+bias), row stride ldc.
// MODE 1: relu(acc+bias) -> split3 -> Ch/Cm/Cl planes (stride 1024).
// MODE 2: fused scores: g_spart[bx*4+wc][row] = sum_cols relu(acc+bias)*Ws3[col].
#define SMA(st, p) ((st) * 55296 + (p) * 6144)
#define SMB(st, p) ((st) * 55296 + 18432 + (p) * 12288)
#define MM_SMEM 110592

template <int MODE>
__global__ __launch_bounds__(256, 1)
void mm3_kernel(const bf16* __restrict__ A0, const bf16* __restrict__ A1,
                const bf16* __restrict__ A2,
                const bf16* __restrict__ B0, const bf16* __restrict__ B1,
                const bf16* __restrict__ B2,
                const float* __restrict__ bias, float* __restrict__ C, int ldc,
                bf16* __restrict__ Ch, bf16* __restrict__ Cm, bf16* __restrict__ Cl,
                const float* __restrict__ Ws3) {
    extern __shared__ char smem[];
    const uint32_t sb = smem_u32(smem);
    const int tid = threadIdx.x;
    const int lane = tid & 31, wid = tid >> 5;
    const int lg = lane >> 2, lt = lane & 3;
    const int wr = wid >> 2, wc = wid & 3;
    const int bm = blockIdx.y * 128, bn = blockIdx.x * 256;

    const bf16* Ap[3] = { A0, A1, A2 };
    const bf16* Bp[3] = { B0, B1, B2 };
    const int arow = tid >> 1, ahalf = tid & 1;

    float acc[4][8][4];
#pragma unroll
    for (int mi = 0; mi < 4; mi++)
#pragma unroll
        for (int ni = 0; ni < 8; ni++)
#pragma unroll
            for (int q = 0; q < 4; q++) acc[mi][ni][q] = 0.f;

    // stage-fill via cp.async
    auto issue = [&](int st, int k0) {
#pragma unroll
        for (int p = 0; p < 3; p++) {
            uint32_t d = sb + SMA(st, p) + arow * 48 + ahalf * 16;
            const bf16* s = Ap[p] + (size_t)(bm + arow) * 1024 + k0 + ahalf * 8;
            CPASYNC16(d, s);
        }
#pragma unroll
        for (int p = 0; p < 3; p++)
#pragma unroll
            for (int h = 0; h < 2; h++) {
                uint32_t d = sb + SMB(st, p) + tid * 48 + h * 16;
                const bf16* s = Bp[p] + (size_t)(bn + tid) * 1024 + k0 + h * 8;
                CPASYNC16(d, s);
            }
        asm volatile("cp.async.commit_group;" ::: "memory");
    };

    issue(0, 0);
    asm volatile("cp.async.wait_group 0;" ::: "memory");
    __syncthreads();

    // ldmatrix lane address components
    const uint32_t aLaneRow = (lane & 7) + (lane & 8);          // +8 for lanes 8-15,24-31
    const uint32_t aLaneCol = ((lane >> 4) & 1) * 16;           // 16B col for lanes 16-31
    const uint32_t bLaneRow = (lane & 7) + (((lane >> 4) & 1) << 3);
    const uint32_t bLaneCol = ((lane >> 3) & 1) * 16;

    for (int c = 0; c < 64; c++) {
        const int cur = c & 1;
        if (c < 63) issue(cur ^ 1, (c + 1) * 16);

        uint32_t aF[3][4][4];
#pragma unroll
        for (int s = 0; s < 3; s++)
#pragma unroll
            for (int mi = 0; mi < 4; mi++) {
                uint32_t addr = sb + SMA(cur, s)
                              + (wr * 64 + mi * 16 + aLaneRow) * 48 + aLaneCol;
                LDMX4(aF[s][mi], addr);
            }
#pragma unroll
        for (int sbp = 0; sbp < 3; sbp++) {
            uint32_t bF[4][4];
#pragma unroll
            for (int nj = 0; nj < 4; nj++) {
                uint32_t addr = sb + SMB(cur, sbp)
                              + (wc * 64 + nj * 16 + bLaneRow) * 48 + bLaneCol;
                LDMX4(bF[nj], addr);
            }
#pragma unroll
            for (int sa = 0; sa < 3; sa++) {
                if (sa == 2 && sbp == 2) continue;   // drop l*l (~2^-32)
#pragma unroll
                for (int mi = 0; mi < 4; mi++)
#pragma unroll
                    for (int nj = 0; nj < 4; nj++) {
                        MMA16816(acc[mi][nj * 2],     aF[sa][mi], bF[nj][0], bF[nj][1]);
                        MMA16816(acc[mi][nj * 2 + 1], aF[sa][mi], bF[nj][2], bF[nj][3]);
                    }
            }
        }
        asm volatile("cp.async.wait_group 0;" ::: "memory");
        __syncthreads();
    }

    // epilogue
    if (MODE == 2) {
        float rsum[4][2];
#pragma unroll
        for (int mi = 0; mi < 4; mi++) { rsum[mi][0] = 0.f; rsum[mi][1] = 0.f; }
#pragma unroll
        for (int ni = 0; ni < 8; ni++) {
            const int col = bn + wc * 64 + ni * 8 + lt * 2;
            const float b0 = bias[col], b1 = bias[col + 1];
            const float w0 = Ws3[col],  w1 = Ws3[col + 1];
#pragma unroll
            for (int mi = 0; mi < 4; mi++) {
                rsum[mi][0] += fmaxf(acc[mi][ni][0] + b0, 0.f) * w0
                             + fmaxf(acc[mi][ni][1] + b1, 0.f) * w1;
                rsum[mi][1] += fmaxf(acc[mi][ni][2] + b0, 0.f) * w0
                             + fmaxf(acc[mi][ni][3] + b1, 0.f) * w1;
            }
        }
#pragma unroll
        for (int mi = 0; mi < 4; mi++)
#pragma unroll
            for (int h = 0; h < 2; h++) {
                float v = rsum[mi][h];
                v += __shfl_xor_sync(0xFFFFFFFFu, v, 1);
                v += __shfl_xor_sync(0xFFFFFFFFu, v, 2);
                rsum[mi][h] = v;
            }
        if (lt == 0) {
            const int slot = blockIdx.x * 4 + wc;
#pragma unroll
            for (int mi = 0; mi < 4; mi++) {
                const int r0 = bm + wr * 64 + mi * 16 + lg;
                g_spart[slot][r0]     = rsum[mi][0];
                g_spart[slot][r0 + 8] = rsum[mi][1];
            }
        }
    } else {
#pragma unroll
        for (int mi = 0; mi < 4; mi++) {
            const int r0 = bm + wr * 64 + mi * 16 + lg;
#pragma unroll
            for (int ni = 0; ni < 8; ni++) {
                const int col = bn + wc * 64 + ni * 8 + lt * 2;
                const float b0 = bias[col], b1 = bias[col + 1];
                float vx0 = acc[mi][ni][0] + b0, vy0 = acc[mi][ni][1] + b1;
                float vx1 = acc[mi][ni][2] + b0, vy1 = acc[mi][ni][3] + b1;
                if (MODE == 0) {
                    *(float2*)&C[(size_t)r0 * ldc + col]       = make_float2(vx0, vy0);
                    *(float2*)&C[(size_t)(r0 + 8) * ldc + col] = make_float2(vx1, vy1);
                } else {
                    vx0 = fmaxf(vx0, 0.f); vy0 = fmaxf(vy0, 0.f);
                    vx1 = fmaxf(vx1, 0.f); vy1 = fmaxf(vy1, 0.f);
                    bf16 h0, m0, l0, h1, m1, l1;
                    bf16split3(vx0, h0, m0, l0); bf16split3(vy0, h1, m1, l1);
                    *(bf162*)&Ch[(size_t)r0 * 1024 + col] = bf162(h0, h1);
                    *(bf162*)&Cm[(size_t)r0 * 1024 + col] = bf162(m0, m1);
                    *(bf162*)&Cl[(size_t)r0 * 1024 + col] = bf162(l0, l1);
                    bf16split3(vx1, h0, m0, l0); bf16split3(vy1, h1, m1, l1);
                    *(bf162*)&Ch[(size_t)(r0 + 8) * 1024 + col] = bf162(h0, h1);
                    *(bf162*)&Cm[(size_t)(r0 + 8) * 1024 + col] = bf162(m0, m1);
                    *(bf162*)&Cl[(size_t)(r0 + 8) * 1024 + col] = bf162(l0, l1);
                }
            }
        }
    }
}

// ---------------- softmax over feature dim, times embeds ----------------
__global__ void softmax_mul_kernel(const float* __restrict__ alpha,
                                   const float* __restrict__ emb,
                                   float* __restrict__ wtd) {
    const int r = blockIdx.x;
    const int tid = threadIdx.x;  // 256
    __shared__ float red[256];
    float4 a = ((const float4*)(alpha + (size_t)r * DD))[tid];
    float m = fmaxf(fmaxf(a.x, a.y), fmaxf(a.z, a.w));
    red[tid] = m;
    __syncthreads();
    for (int s = 128; s > 0; s >>= 1) {
        if (tid < s) red[tid] = fmaxf(red[tid], red[tid + s]);
        __syncthreads();
    }
    const float mx = red[0];
    __syncthreads();
    float4 e;
    e.x = expf(a.x - mx); e.y = expf(a.y - mx);
    e.z = expf(a.z - mx); e.w = expf(a.w - mx);
    red[tid] = e.x + e.y + e.z + e.w;
    __syncthreads();
    for (int s = 128; s > 0; s >>= 1) {
        if (tid < s) red[tid] += red[tid + s];
        __syncthreads();
    }
    const float inv = 1.f / red[0];
    float4 em = ((const float4*)(emb + (size_t)r * DD))[tid];
    float4 o;
    o.x = e.x * inv * em.x; o.y = e.y * inv * em.y;
    o.z = e.z * inv * em.z; o.w = e.w * inv * em.w;
    ((float4*)(wtd + (size_t)r * DD))[tid] = o;
}

// ---------------- column-wise prefix sum (3 passes) ----------------
__global__ void scan_chunks_kernel(const float* __restrict__ wtd, float* __restrict__ csum) {
    const int c = blockIdx.x;
    const int col = blockIdx.y * 128 + threadIdx.x;
    float s = 0.f;
#pragma unroll 8
    for (int r = 0; r < 128; r++) s += wtd[(size_t)(c * 128 + r) * DD + col];
    csum[c * DD + col] = s;
}
__global__ void scan_offsets_kernel(float* __restrict__ csum) {
    const int col = blockIdx.x * 256 + threadIdx.x;
    float run = 0.f;
#pragma unroll
    for (int c = 0; c < 16; c++) {
        float t = csum[c * DD + col];
        csum[c * DD + col] = run;
        run += t;
    }
}
// prefix fp32 + split3 planes (A-operand for the Q GEMM)
__global__ void scan_write3_kernel(const float* __restrict__ wtd, const float* __restrict__ csum,
                                   float* __restrict__ prefix,
                                   bf16* __restrict__ ph, bf16* __restrict__ pm,
                                   bf16* __restrict__ pl) {
    const int c = blockIdx.x;
    const int col = blockIdx.y * 128 + threadIdx.x;
    float run = csum[c * DD + col];
    if (c == 0) {
        prefix[col] = 0.f;
        ph[col] = __float2bfloat16_rn(0.f);
        pm[col] = __float2bfloat16_rn(0.f);
        pl[col] = __float2bfloat16_rn(0.f);
    }
#pragma unroll 8
    for (int r = 0; r < 128; r++) {
        run += wtd[(size_t)(c * 128 + r) * DD + col];
        size_t o = (size_t)(c * 128 + r + 1) * DD + col;
        prefix[o] = run;
        bf16 h, m, l; bf16split3(run, h, m, l);
        ph[o] = h; pm[o] = m; pl[o] = l;
    }
}

// ---------------- span assembly: g output + split3 s1 ----------------
__global__ void assemble_kernel(const float* __restrict__ L,
                                const int* __restrict__ starts,
                                const int* __restrict__ ends,
                                const float* __restrict__ bs1,
                                float* __restrict__ out_g) {
    const int i = blockIdx.x;
    const int t = threadIdx.x;   // 0..255, float4 over 1024 feats
    const int s = starts[i];
    const int e = ends[i];
    const float4* L4  = (const float4*)L;
    const float4* pf4 = (const float4*)g_prefix;
    const float4* PP4 = (const float4*)g_PaPb;   // row stride 512 float4
    const float4* Q4  = (const float4*)g_Q;

    float4 ls = L4[(size_t)s * 256 + t];
    float4 le = L4[(size_t)e * 256 + t];
    float4 pe = pf4[(size_t)(e + 1) * 256 + t];
    float4 ps = pf4[(size_t)s * 256 + t];
    float4 xa = make_float4(pe.x - ps.x, pe.y - ps.y, pe.z - ps.z, pe.w - ps.w);

    float4* go = (float4*)(out_g + (size_t)i * 3072);
    go[t]       = ls;
    go[256 + t] = le;
    go[512 + t] = xa;

    float4 pa = PP4[(size_t)s * 512 + t];         // Pa = cols 0..1023
    float4 pb = PP4[(size_t)e * 512 + 256 + t];   // Pb = cols 1024..2047
    float4 qe = Q4[(size_t)(e + 1) * 256 + t];
    float4 qs = Q4[(size_t)s * 256 + t];
    float4 bb = ((const float4*)bs1)[t];
    float4 v;
    v.x = fmaxf(pa.x + pb.x + qe.x - qs.x + bb.x, 0.f);
    v.y = fmaxf(pa.y + pb.y + qe.y - qs.y + bb.y, 0.f);
    v.z = fmaxf(pa.z + pb.z + qe.z - qs.z + bb.z, 0.f);
    v.w = fmaxf(pa.w + pb.w + qe.w - qs.w + bb.w, 0.f);
    bf16 h0, m0, l0, h1, m1, l1;
    bf16split3(v.x, h0, m0, l0); bf16split3(v.y, h1, m1, l1);
    ((bf162*)g_s1h)[(size_t)i * 512 + t * 2]     = bf162(h0, h1);
    ((bf162*)g_s1m)[(size_t)i * 512 + t * 2]     = bf162(m0, m1);
    ((bf162*)g_s1l)[(size_t)i * 512 + t * 2]     = bf162(l0, l1);
    bf16split3(v.z, h0, m0, l0); bf16split3(v.w, h1, m1, l1);
    ((bf162*)g_s1h)[(size_t)i * 512 + t * 2 + 1] = bf162(h0, h1);
    ((bf162*)g_s1m)[(size_t)i * 512 + t * 2 + 1] = bf162(m0, m1);
    ((bf162*)g_s1l)[(size_t)i * 512 + t * 2 + 1] = bf162(l0, l1);
}

// ---------------- deterministic score reduction ----------------
__global__ void scores_reduce_kernel(const float* __restrict__ bs3, float* __restrict__ out) {
    const int i = blockIdx.x * 256 + threadIdx.x;
    float s = bs3[0];
#pragma unroll
    for (int k = 0; k < 16; k++) s += g_spart[k][i];
    out[i] = s;
}

// ---------------- top-k: 16-bit histogram select + exact rank among candidates ----------------
__device__ __forceinline__ uint32_t fsort(float f) {
    uint32_t u = __float_as_uint(f);
    return (u & 0x80000000u) ? ~u : (u | 0x80000000u);
}
__global__ void hist_zero_kernel() {
    const int i = blockIdx.x * 256 + threadIdx.x;
    if (i < 65536) g_hist[i] = 0;
    if (i == 0) g_ccount[0] = 0;
}
__global__ void hist_build_kernel(const float* __restrict__ sc) {
    const int i = blockIdx.x * 256 + threadIdx.x;
    atomicAdd(&g_hist[fsort(sc[i]) >> 16], 1);
}
__global__ void hist_cut_kernel() {
    __shared__ int part[1024];
    __shared__ int suf[1024];
    const int t = threadIdx.x;
    int s = 0;
#pragma unroll
    for (int j = 0; j < 64; j++) s += g_hist[t * 64 + j];
    part[t] = s;
    __syncthreads();
    if (t == 0) {
        int run = 0;
        for (int i = 1023; i >= 0; i--) { suf[i] = run; run += part[i]; }
    }
    __syncthreads();
    int cum = suf[t];   // scores strictly above group t
    for (int j = 63; j >= 0; j--) {
        int h = g_hist[t * 64 + j];
        int ncum = cum + h;
        if (cum < KPRUNE && ncum >= KPRUNE) g_cut[0] = t * 64 + j;
        cum = ncum;
    }
}
__global__ void cand_build_kernel(const float* __restrict__ sc) {
    const int i = blockIdx.x * 256 + threadIdx.x;
    float v = sc[i];
    if ((int)(fsort(v) >> 16) >= g_cut[0]) {
        int p = atomicAdd(&g_ccount[0], 1);
        g_cscore[p] = v;
        g_cidx[p] = i;
    }
}
__global__ void cand_rank_kernel(float* __restrict__ out_idx) {
    __shared__ float shs[4096];
    __shared__ int shi[4096];
    const int nc = g_ccount[0];
    for (int ib = 0; ib < nc; ib += 1024) {
        const int i = ib + (int)threadIdx.x;
        const bool act = (i < nc);
        float my = act ? g_cscore[i] : 0.f;
        int myi = act ? g_cidx[i] : 0x7FFFFFFF;
        int rank = 0;
        for (int c0 = 0; c0 < nc; c0 += 4096) {
            int n = min(4096, nc - c0);
            __syncthreads();
            for (int j = threadIdx.x; j < (unsigned)n; j += 1024) {
                shs[j] = g_cscore[c0 + j];
                shi[j] = g_cidx[c0 + j];
            }
            __syncthreads();
            for (int j = 0; j < n; j++) {
                float v = shs[j];
                rank += (v > my) || (v == my && shi[j] < myi);
            }
        }
        if (act && rank < KPRUNE) out_idx[rank] = (float)myi;
    }
}

// ---------------- launch ----------------
static void* sym_addr(const void* symbol) {
    void* p = nullptr;
    cudaGetSymbolAddress(&p, symbol);
    return p;
}

extern "C" void kernel_launch(void* const* d_in, const int* in_sizes, int n_in,
                              void* d_out, int out_size) {
    const float* L    = (const float*)d_in[0];
    const float* emb  = (const float*)d_in[1];
    const float* Wa1  = (const float*)d_in[2];
    const float* ba1  = (const float*)d_in[3];
    const float* Wa2  = (const float*)d_in[4];
    const float* ba2  = (const float*)d_in[5];
    const float* Wa3  = (const float*)d_in[6];
    const float* ba3  = (const float*)d_in[7];
    const float* Ws1  = (const float*)d_in[8];
    const float* bs1  = (const float*)d_in[9];
    const float* Ws2  = (const float*)d_in[10];
    const float* bs2  = (const float*)d_in[11];
    const float* Ws3  = (const float*)d_in[12];
    const float* bs3  = (const float*)d_in[13];
    const int* starts = (const int*)d_in[14];
    const int* ends   = (const int*)d_in[15];

    float* out        = (float*)d_out;
    float* out_scores = out;
    float* out_g      = out + SS;
    float* out_idx    = out + SS + (size_t)SS * 3072;

    bf16* Lh = (bf16*)sym_addr(g_Lh); bf16* Lm = (bf16*)sym_addr(g_Lm); bf16* Ll = (bf16*)sym_addr(g_Ll);
    bf16* Wh = (bf16*)sym_addr(g_Wh); bf16* Wm = (bf16*)sym_addr(g_Wm); bf16* Wl = (bf16*)sym_addr(g_Wl);
    bf16* h1h = (bf16*)sym_addr(g_h1h); bf16* h1m = (bf16*)sym_addr(g_h1m); bf16* h1l = (bf16*)sym_addr(g_h1l);
    bf16* h2h = (bf16*)sym_addr(g_h2h); bf16* h2m = (bf16*)sym_addr(g_h2m); bf16* h2l = (bf16*)sym_addr(g_h2l);
    bf16* pfh = (bf16*)sym_addr(g_pfh); bf16* pfm = (bf16*)sym_addr(g_pfm); bf16* pfl = (bf16*)sym_addr(g_pfl);
    bf16* s1h = (bf16*)sym_addr(g_s1h); bf16* s1m = (bf16*)sym_addr(g_s1m); bf16* s1l = (bf16*)sym_addr(g_s1l);
    float* PaPb = (float*)sym_addr(g_PaPb);
    float* alp  = (float*)sym_addr(g_alpha);
    float* wtd  = (float*)sym_addr(g_wtd);
    float* pfx  = (float*)sym_addr(g_prefix);
    float* cs   = (float*)sym_addr(g_csum);
    float* Q    = (float*)sym_addr(g_Q);
    float* zb   = (float*)sym_addr(g_zbias);

    cudaFuncSetAttribute(mm3_kernel<0>, cudaFuncAttributeMaxDynamicSharedMemorySize, MM_SMEM);
    cudaFuncSetAttribute(mm3_kernel<1>, cudaFuncAttributeMaxDynamicSharedMemorySize, MM_SMEM);
    cudaFuncSetAttribute(mm3_kernel<2>, cudaFuncAttributeMaxDynamicSharedMemorySize, MM_SMEM);

    const size_t WSZ = (size_t)DD * DD;

    // one-shot operand prep
    split3_kernel<<<T_TOK * DD / 2 / 256, 256>>>(L, Lh, Lm, Ll, T_TOK * DD / 2);
    // slots: 0=Wa1, 1=Ws1a, 2=Ws1b, 3=Wa2, 4=Wa3, 5=Ws1c, 6=Ws2
    const float* wsrc[7] = { Wa1, Ws1, Ws1 + WSZ, Wa2, Wa3, Ws1 + 2 * WSZ, Ws2 };
    for (int k = 0; k < 7; k++)
        transpose_split3_kernel<<<dim3(32, 32), dim3(32, 8)>>>(
            wsrc[k], Wh + k * WSZ, Wm + k * WSZ, Wl + k * WSZ);

    // h1 = relu(L @ Wa1 + ba1) -> planes
    mm3_kernel<1><<<dim3(4, 16), 256, MM_SMEM>>>(Lh, Lm, Ll, Wh, Wm, Wl,
                                                 ba1, nullptr, 0, h1h, h1m, h1l, zb);
    // [Pa|Pb] = L @ [Ws1a|Ws1b]  (fp32, ldc 2048)
    mm3_kernel<0><<<dim3(8, 16), 256, MM_SMEM>>>(Lh, Lm, Ll, Wh + WSZ, Wm + WSZ, Wl + WSZ,
                                                 zb, PaPb, 2048, nullptr, nullptr, nullptr, zb);
    // h2 = relu(h1 @ Wa2 + ba2) -> planes
    mm3_kernel<1><<<dim3(4, 16), 256, MM_SMEM>>>(h1h, h1m, h1l, Wh + 3 * WSZ, Wm + 3 * WSZ, Wl + 3 * WSZ,
                                                 ba2, nullptr, 0, h2h, h2m, h2l, zb);
    // alpha = h2 @ Wa3 + ba3
    mm3_kernel<0><<<dim3(4, 16), 256, MM_SMEM>>>(h2h, h2m, h2l, Wh + 4 * WSZ, Wm + 4 * WSZ, Wl + 4 * WSZ,
                                                 ba3, alp, 1024, nullptr, nullptr, nullptr, zb);
    softmax_mul_kernel<<<T_TOK, 256>>>(alp, emb, wtd);

    // prefix sums over tokens (fp32 + split3 planes)
    scan_chunks_kernel<<<dim3(16, 8), 128>>>(wtd, cs);
    scan_offsets_kernel<<<4, 256>>>(cs);
    scan_write3_kernel<<<dim3(16, 8), 128>>>(wtd, cs, pfx, pfh, pfm, pfl);

    // Q = prefix @ Ws1c  (rows >= 2049 garbage but never read)
    mm3_kernel<0><<<dim3(4, 17), 256, MM_SMEM>>>(pfh, pfm, pfl, Wh + 5 * WSZ, Wm + 5 * WSZ, Wl + 5 * WSZ,
                                                 zb, Q, 1024, nullptr, nullptr, nullptr, zb);

    // g output + split3 s1
    assemble_kernel<<<SS, 256>>>(L, starts, ends, bs1, out_g);

    // fused second layer + score dot (dominant GEMM)
    mm3_kernel<2><<<dim3(4, 160), 256, MM_SMEM>>>(s1h, s1m, s1l, Wh + 6 * WSZ, Wm + 6 * WSZ, Wl + 6 * WSZ,
                                                  bs2, nullptr, 0, nullptr, nullptr, nullptr, Ws3);
    scores_reduce_kernel<<<SS / 256, 256>>>(bs3, out_scores);

    // exact top-k
    hist_zero_kernel<<<256, 256>>>();
    hist_build_kernel<<<SS / 256, 256>>>(out_scores);
    hist_cut_kernel<<<1, 1024>>>();
    cand_build_kernel<<<SS / 256, 256>>>(out_scores);
    cand_rank_kernel<<<1, 1024>>>(out_idx);
}

// round 7
// speedup vs baseline: 1.0888x; 1.0789x over previous
#include <cuda_runtime.h>
#include <cuda_bf16.h>
#include <math.h>
#include <stdint.h>

#define T_TOK 2048
#define DD    1024
#define SS    20480
#define KPRUNE 819
#define CTARGET (KPRUNE + 256)
#define MAXC  4096
#define MPAD_Q 2176

typedef __nv_bfloat16 bf16;
typedef __nv_bfloat162 bf162;

// ---------------- scratch (device globals) ----------------
__device__ __align__(16) bf16 g_Lh[T_TOK * DD], g_Lm[T_TOK * DD];
__device__ __align__(16) bf16 g_WBh[(size_t)4096 * DD], g_WBm[(size_t)4096 * DD];
__device__ __align__(16) bf16 g_pfh[MPAD_Q * DD], g_pfm[MPAD_Q * DD];
__device__ __align__(16) bf16 g_s1h[(size_t)SS * DD], g_s1m[(size_t)SS * DD];
__device__ float g_h1[T_TOK * DD];
__device__ float g_h2[T_TOK * DD];
__device__ float g_alpha[T_TOK * DD];
__device__ float g_wtd[T_TOK * DD];
__device__ float g_prefix[(T_TOK + 1) * DD];
__device__ float g_csum[16 * DD];
__device__ float g_PaPb[(size_t)T_TOK * 2048];
__device__ float g_Q[MPAD_Q * DD];
__device__ float g_spart[16][SS];
__device__ float g_s1c[(size_t)MAXC * DD];
__device__ float g_rpart[8][MAXC];
__device__ float g_cexact[MAXC];
__device__ float g_zbias[2048];     // zero-initialized, never written
__device__ int   g_hist[65536];
__device__ int   g_cut[1];
__device__ int   g_ccount[1];
__device__ int   g_cidx[MAXC];

// ---------------- helpers ----------------
__device__ __forceinline__ uint32_t smem_u32(const void* p) {
    uint32_t a;
    asm("{ .reg .u64 t; cvta.to.shared.u64 t, %1; cvt.u32.u64 %0, t; }" : "=r"(a) : "l"(p));
    return a;
}
__device__ __forceinline__ void bf16split2(float x, bf16& h, bf16& m) {
    h = __float2bfloat16_rn(x);
    m = __float2bfloat16_rn(x - __bfloat162float(h));
}

#define LDMX4(r, addr)                                                        \
    asm volatile("ldmatrix.sync.aligned.m8n8.x4.shared.b16 {%0,%1,%2,%3}, [%4];" \
        : "=r"((r)[0]), "=r"((r)[1]), "=r"((r)[2]), "=r"((r)[3]) : "r"(addr))

#define MMA16816(c, a, b0, b1)                                                \
    asm volatile("mma.sync.aligned.m16n8k16.row.col.f32.bf16.bf16.f32 "       \
        "{%0,%1,%2,%3},{%4,%5,%6,%7},{%8,%9},{%0,%1,%2,%3};"                  \
        : "+f"((c)[0]), "+f"((c)[1]), "+f"((c)[2]), "+f"((c)[3])              \
        : "r"((a)[0]), "r"((a)[1]), "r"((a)[2]), "r"((a)[3]), "r"(b0), "r"(b1))

#define CPASYNC16(dst, src)                                                   \
    asm volatile("cp.async.cg.shared.global [%0],[%1],16;" :: "r"(dst), "l"(src) : "memory")

// ---------------- R1 fp32 FFMA sgemm (proven precision) ----------------
template <int RELU>
__global__ __launch_bounds__(256, 2)
void sgemm_kernel(const float* __restrict__ A, const float* __restrict__ B,
                  const float* __restrict__ bias, float* __restrict__ C,
                  int M, int K, int N) {
    __shared__ float As[8][128];
    __shared__ float Bs[8][128];
    const int tid = threadIdx.x;
    const int bm = blockIdx.y * 128;
    const int bn = blockIdx.x * 128;
    const int tx = tid & 15;
    const int ty = tid >> 4;
    const int aRow = tid >> 1;
    const int aCol = (tid & 1) * 4;
    const int bRow = tid >> 5;
    const int bCol = (tid & 31) * 4;

    float acc[8][8];
#pragma unroll
    for (int i = 0; i < 8; i++)
#pragma unroll
        for (int j = 0; j < 8; j++) acc[i][j] = 0.f;

    for (int k0 = 0; k0 < K; k0 += 8) {
        float4 av = make_float4(0.f, 0.f, 0.f, 0.f);
        if (bm + aRow < M)
            av = *(const float4*)&A[(size_t)(bm + aRow) * K + k0 + aCol];
        As[aCol + 0][aRow] = av.x;
        As[aCol + 1][aRow] = av.y;
        As[aCol + 2][aRow] = av.z;
        As[aCol + 3][aRow] = av.w;
        *(float4*)&Bs[bRow][bCol] = *(const float4*)&B[(size_t)(k0 + bRow) * N + bn + bCol];
        __syncthreads();
#pragma unroll
        for (int k = 0; k < 8; k++) {
            float a[8], b[8];
            *(float4*)(a)     = *(float4*)&As[k][ty * 8];
            *(float4*)(a + 4) = *(float4*)&As[k][ty * 8 + 4];
            *(float4*)(b)     = *(float4*)&Bs[k][tx * 8];
            *(float4*)(b + 4) = *(float4*)&Bs[k][tx * 8 + 4];
#pragma unroll
            for (int i = 0; i < 8; i++)
#pragma unroll
                for (int j = 0; j < 8; j++) acc[i][j] += a[i] * b[j];
        }
        __syncthreads();
    }
#pragma unroll
    for (int i = 0; i < 8; i++) {
        int row = bm + ty * 8 + i;
        if (row < M) {
#pragma unroll
            for (int j = 0; j < 8; j++) {
                float v = acc[i][j] + bias[bn + tx * 8 + j];
                if (RELU) v = fmaxf(v, 0.f);
                acc[i][j] = v;
            }
            *(float4*)&C[(size_t)row * N + bn + tx * 8]     = *(float4*)&acc[i][0];
            *(float4*)&C[(size_t)row * N + bn + tx * 8 + 4] = *(float4*)&acc[i][4];
        }
    }
}

// ---------------- prep kernels ----------------
__global__ void split2_kernel(const float* __restrict__ in,
                              bf16* __restrict__ oh, bf16* __restrict__ om, int n2) {
    int i = blockIdx.x * 256 + threadIdx.x;
    if (i >= n2) return;
    float2 v = ((const float2*)in)[i];
    bf16 hx, mx, hy, my;
    bf16split2(v.x, hx, mx);
    bf16split2(v.y, hy, my);
    ((bf162*)oh)[i] = bf162(hx, hy);
    ((bf162*)om)[i] = bf162(mx, my);
}

// out planes [N][K] = split2(in[K][N])
__global__ void transpose_split2_kernel(const float* __restrict__ in,
                                        bf16* __restrict__ oh, bf16* __restrict__ om) {
    __shared__ float t[32][33];
    int bx = blockIdx.x * 32, by = blockIdx.y * 32;
#pragma unroll
    for (int i = 0; i < 32; i += 8)
        t[threadIdx.y + i][threadIdx.x] = in[(size_t)(by + threadIdx.y + i) * DD + bx + threadIdx.x];
    __syncthreads();
#pragma unroll
    for (int i = 0; i < 32; i += 8) {
        float v = t[threadIdx.x][threadIdx.y + i];
        bf16 h, m; bf16split2(v, h, m);
        size_t o = (size_t)(bx + threadIdx.y + i) * DD + by + threadIdx.x;
        oh[o] = h; om[o] = m;
    }
}

// ---------------- approx GEMM: 3-MMA bf16 (hh + hm + mh) ----------------
// C[M x N] = A[M x 1024] @ B[N][1024]^T (+bias). CTA 128x256, 8 warps 64x64, BK=16.
// MODE 0: store fp32 C (+bias). MODE 2: fused g_spart scores.
#define SMA2(st, p) ((st) * 36864 + (p) * 6144)
#define SMB2(st, p) ((st) * 36864 + 12288 + (p) * 12288)
#define MM_SMEM2 73728

template <int MODE>
__global__ __launch_bounds__(256, 1)
void mmT3_kernel(const bf16* __restrict__ A0, const bf16* __restrict__ A1,
                 const bf16* __restrict__ B0, const bf16* __restrict__ B1,
                 const float* __restrict__ bias, float* __restrict__ C, int ldc,
                 const float* __restrict__ Ws3) {
    extern __shared__ char smem[];
    const uint32_t sb = smem_u32(smem);
    const int tid = threadIdx.x;
    const int lane = tid & 31, wid = tid >> 5;
    const int lg = lane >> 2, lt = lane & 3;
    const int wr = wid >> 2, wc = wid & 3;
    const int bm = blockIdx.y * 128, bn = blockIdx.x * 256;

    const bf16* Ap[2] = { A0, A1 };
    const bf16* Bp[2] = { B0, B1 };
    const int arow = tid >> 1, ahalf = tid & 1;

    float acc[4][8][4];
#pragma unroll
    for (int mi = 0; mi < 4; mi++)
#pragma unroll
        for (int ni = 0; ni < 8; ni++)
#pragma unroll
            for (int q = 0; q < 4; q++) acc[mi][ni][q] = 0.f;

    auto issue = [&](int st, int k0) {
#pragma unroll
        for (int p = 0; p < 2; p++) {
            uint32_t d = sb + SMA2(st, p) + arow * 48 + ahalf * 16;
            CPASYNC16(d, Ap[p] + (size_t)(bm + arow) * 1024 + k0 + ahalf * 8);
        }
#pragma unroll
        for (int p = 0; p < 2; p++)
#pragma unroll
            for (int h = 0; h < 2; h++) {
                uint32_t d = sb + SMB2(st, p) + tid * 48 + h * 16;
                CPASYNC16(d, Bp[p] + (size_t)(bn + tid) * 1024 + k0 + h * 8);
            }
        asm volatile("cp.async.commit_group;" ::: "memory");
    };

    issue(0, 0);
    asm volatile("cp.async.wait_group 0;" ::: "memory");
    __syncthreads();

    const uint32_t aLaneRow = (lane & 7) + (lane & 8);
    const uint32_t aLaneCol = ((lane >> 4) & 1) * 16;
    const uint32_t bLaneRow = (lane & 7) + (((lane >> 4) & 1) << 3);
    const uint32_t bLaneCol = ((lane >> 3) & 1) * 16;

    for (int c = 0; c < 64; c++) {
        const int cur = c & 1;
        if (c < 63) issue(cur ^ 1, (c + 1) * 16);

        uint32_t aFh[4][4], aFm[4][4];
#pragma unroll
        for (int mi = 0; mi < 4; mi++) {
            uint32_t r = (wr * 64 + mi * 16 + aLaneRow) * 48 + aLaneCol;
            LDMX4(aFh[mi], sb + SMA2(cur, 0) + r);
            LDMX4(aFm[mi], sb + SMA2(cur, 1) + r);
        }
#pragma unroll
        for (int nj = 0; nj < 4; nj++) {
            uint32_t bFh[4], bFm[4];
            uint32_t r = (wc * 64 + nj * 16 + bLaneRow) * 48 + bLaneCol;
            LDMX4(bFh, sb + SMB2(cur, 0) + r);
            LDMX4(bFm, sb + SMB2(cur, 1) + r);
#pragma unroll
            for (int mi = 0; mi < 4; mi++) {
                MMA16816(acc[mi][nj * 2],     aFh[mi], bFh[0], bFh[1]);
                MMA16816(acc[mi][nj * 2 + 1], aFh[mi], bFh[2], bFh[3]);
                MMA16816(acc[mi][nj * 2],     aFh[mi], bFm[0], bFm[1]);
                MMA16816(acc[mi][nj * 2 + 1], aFh[mi], bFm[2], bFm[3]);
                MMA16816(acc[mi][nj * 2],     aFm[mi], bFh[0], bFh[1]);
                MMA16816(acc[mi][nj * 2 + 1], aFm[mi], bFh[2], bFh[3]);
            }
        }
        asm volatile("cp.async.wait_group 0;" ::: "memory");
        __syncthreads();
    }

    if (MODE == 2) {
        float rsum[4][2];
#pragma unroll
        for (int mi = 0; mi < 4; mi++) { rsum[mi][0] = 0.f; rsum[mi][1] = 0.f; }
#pragma unroll
        for (int ni = 0; ni < 8; ni++) {
            const int col = bn + wc * 64 + ni * 8 + lt * 2;
            const float b0 = bias[col], b1 = bias[col + 1];
            const float w0 = Ws3[col],  w1 = Ws3[col + 1];
#pragma unroll
            for (int mi = 0; mi < 4; mi++) {
                rsum[mi][0] += fmaxf(acc[mi][ni][0] + b0, 0.f) * w0
                             + fmaxf(acc[mi][ni][1] + b1, 0.f) * w1;
                rsum[mi][1] += fmaxf(acc[mi][ni][2] + b0, 0.f) * w0
                             + fmaxf(acc[mi][ni][3] + b1, 0.f) * w1;
            }
        }
#pragma unroll
        for (int mi = 0; mi < 4; mi++)
#pragma unroll
            for (int h = 0; h < 2; h++) {
                float v = rsum[mi][h];
                v += __shfl_xor_sync(0xFFFFFFFFu, v, 1);
                v += __shfl_xor_sync(0xFFFFFFFFu, v, 2);
                rsum[mi][h] = v;
            }
        if (lt == 0) {
            const int slot = blockIdx.x * 4 + wc;
#pragma unroll
            for (int mi = 0; mi < 4; mi++) {
                const int r0 = bm + wr * 64 + mi * 16 + lg;
                g_spart[slot][r0]     = rsum[mi][0];
                g_spart[slot][r0 + 8] = rsum[mi][1];
            }
        }
    } else {
#pragma unroll
        for (int mi = 0; mi < 4; mi++) {
            const int r0 = bm + wr * 64 + mi * 16 + lg;
#pragma unroll
            for (int ni = 0; ni < 8; ni++) {
                const int col = bn + wc * 64 + ni * 8 + lt * 2;
                const float b0 = bias[col], b1 = bias[col + 1];
                *(float2*)&C[(size_t)r0 * ldc + col] =
                    make_float2(acc[mi][ni][0] + b0, acc[mi][ni][1] + b1);
                *(float2*)&C[(size_t)(r0 + 8) * ldc + col] =
                    make_float2(acc[mi][ni][2] + b0, acc[mi][ni][3] + b1);
            }
        }
    }
}

// ---------------- softmax over feature dim, times embeds ----------------
__global__ void softmax_mul_kernel(const float* __restrict__ alpha,
                                   const float* __restrict__ emb,
                                   float* __restrict__ wtd) {
    const int r = blockIdx.x;
    const int tid = threadIdx.x;
    __shared__ float red[256];
    float4 a = ((const float4*)(alpha + (size_t)r * DD))[tid];
    float m = fmaxf(fmaxf(a.x, a.y), fmaxf(a.z, a.w));
    red[tid] = m;
    __syncthreads();
    for (int s = 128; s > 0; s >>= 1) {
        if (tid < s) red[tid] = fmaxf(red[tid], red[tid + s]);
        __syncthreads();
    }
    const float mx = red[0];
    __syncthreads();
    float4 e;
    e.x = expf(a.x - mx); e.y = expf(a.y - mx);
    e.z = expf(a.z - mx); e.w = expf(a.w - mx);
    red[tid] = e.x + e.y + e.z + e.w;
    __syncthreads();
    for (int s = 128; s > 0; s >>= 1) {
        if (tid < s) red[tid] += red[tid + s];
        __syncthreads();
    }
    const float inv = 1.f / red[0];
    float4 em = ((const float4*)(emb + (size_t)r * DD))[tid];
    float4 o;
    o.x = e.x * inv * em.x; o.y = e.y * inv * em.y;
    o.z = e.z * inv * em.z; o.w = e.w * inv * em.w;
    ((float4*)(wtd + (size_t)r * DD))[tid] = o;
}

// ---------------- column-wise prefix sum ----------------
__global__ void scan_chunks_kernel(const float* __restrict__ wtd, float* __restrict__ csum) {
    const int c = blockIdx.x;
    const int col = blockIdx.y * 128 + threadIdx.x;
    float s = 0.f;
#pragma unroll 8
    for (int r = 0; r < 128; r++) s += wtd[(size_t)(c * 128 + r) * DD + col];
    csum[c * DD + col] = s;
}
__global__ void scan_offsets_kernel(float* __restrict__ csum) {
    const int col = blockIdx.x * 256 + threadIdx.x;
    float run = 0.f;
#pragma unroll
    for (int c = 0; c < 16; c++) {
        float t = csum[c * DD + col];
        csum[c * DD + col] = run;
        run += t;
    }
}
__global__ void scan_write2_kernel(const float* __restrict__ wtd, const float* __restrict__ csum,
                                   float* __restrict__ prefix,
                                   bf16* __restrict__ ph, bf16* __restrict__ pm) {
    const int c = blockIdx.x;
    const int col = blockIdx.y * 128 + threadIdx.x;
    float run = csum[c * DD + col];
    if (c == 0) {
        prefix[col] = 0.f;
        ph[col] = __float2bfloat16_rn(0.f);
        pm[col] = __float2bfloat16_rn(0.f);
    }
#pragma unroll 8
    for (int r = 0; r < 128; r++) {
        run += wtd[(size_t)(c * 128 + r) * DD + col];
        size_t o = (size_t)(c * 128 + r + 1) * DD + col;
        prefix[o] = run;
        bf16 h, m; bf16split2(run, h, m);
        ph[o] = h; pm[o] = m;
    }
}

// ---------------- span assembly: g output + split2 approx s1 ----------------
__global__ void assemble_kernel(const float* __restrict__ L,
                                const int* __restrict__ starts,
                                const int* __restrict__ ends,
                                const float* __restrict__ bs1,
                                float* __restrict__ out_g) {
    const int i = blockIdx.x;
    const int t = threadIdx.x;
    const int s = starts[i];
    const int e = ends[i];
    const float4* L4  = (const float4*)L;
    const float4* pf4 = (const float4*)g_prefix;
    const float4* PP4 = (const float4*)g_PaPb;
    const float4* Q4  = (const float4*)g_Q;

    float4 ls = L4[(size_t)s * 256 + t];
    float4 le = L4[(size_t)e * 256 + t];
    float4 pe = pf4[(size_t)(e + 1) * 256 + t];
    float4 ps = pf4[(size_t)s * 256 + t];
    float4 xa = make_float4(pe.x - ps.x, pe.y - ps.y, pe.z - ps.z, pe.w - ps.w);

    float4* go = (float4*)(out_g + (size_t)i * 3072);
    go[t]       = ls;
    go[256 + t] = le;
    go[512 + t] = xa;

    float4 pa = PP4[(size_t)s * 512 + t];
    float4 pb = PP4[(size_t)e * 512 + 256 + t];
    float4 qe = Q4[(size_t)(e + 1) * 256 + t];
    float4 qs = Q4[(size_t)s * 256 + t];
    float4 bb = ((const float4*)bs1)[t];
    float4 v;
    v.x = fmaxf(pa.x + pb.x + qe.x - qs.x + bb.x, 0.f);
    v.y = fmaxf(pa.y + pb.y + qe.y - qs.y + bb.y, 0.f);
    v.z = fmaxf(pa.z + pb.z + qe.z - qs.z + bb.z, 0.f);
    v.w = fmaxf(pa.w + pb.w + qe.w - qs.w + bb.w, 0.f);
    bf16 h0, m0, h1, m1;
    bf16split2(v.x, h0, m0); bf16split2(v.y, h1, m1);
    ((bf162*)g_s1h)[(size_t)i * 512 + t * 2]     = bf162(h0, h1);
    ((bf162*)g_s1m)[(size_t)i * 512 + t * 2]     = bf162(m0, m1);
    bf16split2(v.z, h0, m0); bf16split2(v.w, h1, m1);
    ((bf162*)g_s1h)[(size_t)i * 512 + t * 2 + 1] = bf162(h0, h1);
    ((bf162*)g_s1m)[(size_t)i * 512 + t * 2 + 1] = bf162(m0, m1);
}

// ---------------- approx score reduction ----------------
__global__ void scores_reduce_kernel(const float* __restrict__ bs3, float* __restrict__ out) {
    const int i = blockIdx.x * 256 + threadIdx.x;
    float s = bs3[0];
#pragma unroll
    for (int k = 0; k < 16; k++) s += g_spart[k][i];
    out[i] = s;
}

// ---------------- candidate selection on approx scores ----------------
__device__ __forceinline__ uint32_t fsort(float f) {
    uint32_t u = __float_as_uint(f);
    return (u & 0x80000000u) ? ~u : (u | 0x80000000u);
}
__global__ void hist_zero_kernel() {
    const int i = blockIdx.x * 256 + threadIdx.x;
    if (i < 65536) g_hist[i] = 0;
    if (i == 0) g_ccount[0] = 0;
}
__global__ void hist_build_kernel(const float* __restrict__ sc) {
    const int i = blockIdx.x * 256 + threadIdx.x;
    atomicAdd(&g_hist[fsort(sc[i]) >> 16], 1);
}
__global__ void hist_cut_kernel() {
    __shared__ int part[1024];
    __shared__ int suf[1024];
    const int t = threadIdx.x;
    int s = 0;
#pragma unroll
    for (int j = 0; j < 64; j++) s += g_hist[t * 64 + j];
    part[t] = s;
    __syncthreads();
    if (t == 0) {
        int run = 0;
        for (int i = 1023; i >= 0; i--) { suf[i] = run; run += part[i]; }
    }
    __syncthreads();
    int cum = suf[t];
    for (int j = 63; j >= 0; j--) {
        int h = g_hist[t * 64 + j];
        int ncum = cum + h;
        if (cum < CTARGET && ncum >= CTARGET) g_cut[0] = t * 64 + j;
        cum = ncum;
    }
}
__global__ void cand_build_kernel(const float* __restrict__ sc) {
    const int i = blockIdx.x * 256 + threadIdx.x;
    if ((int)(fsort(sc[i]) >> 16) >= g_cut[0]) {
        int p = atomicAdd(&g_ccount[0], 1);
        if (p < MAXC) g_cidx[p] = i;
    }
}

// ---------------- rescue layer 1: s1c = relu(g[cidx] @ Ws1 + bs1) ----------------
__global__ __launch_bounds__(256, 4)
void rescue1_kernel(const float* __restrict__ g_all, const float* __restrict__ Ws1,
                    const float* __restrict__ bs1) {
    __shared__ float As[8][68];
    __shared__ float Bs[8][128];
    const int Nc = min(g_ccount[0], MAXC);
    const int bm = blockIdx.y * 64;
    if (bm >= Nc) return;
    const int bn = blockIdx.x * 128;
    const int tid = threadIdx.x;
    const int tx = tid & 15, ty = tid >> 4;
    const int aRow = tid >> 2, aCol = (tid & 3) * 2;
    const int bRow = tid >> 5, bCol = (tid & 31) * 4;
    const int gi = g_cidx[min(bm + aRow, Nc - 1)];
    const float* Arow = g_all + (size_t)gi * 3072 + aCol;

    float acc[4][8];
#pragma unroll
    for (int i = 0; i < 4; i++)
#pragma unroll
        for (int j = 0; j < 8; j++) acc[i][j] = 0.f;

    for (int k0 = 0; k0 < 3072; k0 += 8) {
        float2 av = *(const float2*)(Arow + k0);
        As[aCol][aRow] = av.x;
        As[aCol + 1][aRow] = av.y;
        *(float4*)&Bs[bRow][bCol] = *(const float4*)&Ws1[(size_t)(k0 + bRow) * 1024 + bn + bCol];
        __syncthreads();
#pragma unroll
        for (int k = 0; k < 8; k++) {
            float a[4], b[8];
#pragma unroll
            for (int i = 0; i < 4; i++) a[i] = As[k][ty * 4 + i];
            *(float4*)(b)     = *(float4*)&Bs[k][tx * 8];
            *(float4*)(b + 4) = *(float4*)&Bs[k][tx * 8 + 4];
#pragma unroll
            for (int i = 0; i < 4; i++)
#pragma unroll
                for (int j = 0; j < 8; j++) acc[i][j] += a[i] * b[j];
        }
        __syncthreads();
    }
#pragma unroll
    for (int i = 0; i < 4; i++) {
        int row = bm + ty * 4 + i;
        if (row < Nc) {
#pragma unroll
            for (int j = 0; j < 8; j++)
                acc[i][j] = fmaxf(acc[i][j] + bs1[bn + tx * 8 + j], 0.f);
            *(float4*)&g_s1c[(size_t)row * 1024 + bn + tx * 8]     = *(float4*)&acc[i][0];
            *(float4*)&g_s1c[(size_t)row * 1024 + bn + tx * 8 + 4] = *(float4*)&acc[i][4];
        }
    }
}

// ---------------- rescue layer 2: partials of Ws3 . relu(s1c @ Ws2 + bs2) ----------------
__global__ __launch_bounds__(256, 4)
void rescue2_kernel(const float* __restrict__ Ws2, const float* __restrict__ bs2,
                    const float* __restrict__ Ws3) {
    __shared__ float As[8][68];
    __shared__ float Bs[8][128];
    __shared__ float rsm[64][17];
    const int Nc = min(g_ccount[0], MAXC);
    const int bm = blockIdx.y * 64;
    if (bm >= Nc) return;
    const int bn = blockIdx.x * 128;
    const int tid = threadIdx.x;
    const int tx = tid & 15, ty = tid >> 4;
    const int aRow = tid >> 2, aCol = (tid & 3) * 2;
    const int bRow = tid >> 5, bCol = (tid & 31) * 4;
    const float* Arow = g_s1c + (size_t)min(bm + aRow, Nc - 1) * 1024 + aCol;

    float acc[4][8];
#pragma unroll
    for (int i = 0; i < 4; i++)
#pragma unroll
        for (int j = 0; j < 8; j++) acc[i][j] = 0.f;

    for (int k0 = 0; k0 < 1024; k0 += 8) {
        float2 av = *(const float2*)(Arow + k0);
        As[aCol][aRow] = av.x;
        As[aCol + 1][aRow] = av.y;
        *(float4*)&Bs[bRow][bCol] = *(const float4*)&Ws2[(size_t)(k0 + bRow) * 1024 + bn + bCol];
        __syncthreads();
#pragma unroll
        for (int k = 0; k < 8; k++) {
            float a[4], b[8];
#pragma unroll
            for (int i = 0; i < 4; i++) a[i] = As[k][ty * 4 + i];
            *(float4*)(b)     = *(float4*)&Bs[k][tx * 8];
            *(float4*)(b + 4) = *(float4*)&Bs[k][tx * 8 + 4];
#pragma unroll
            for (int i = 0; i < 4; i++)
#pragma unroll
                for (int j = 0; j < 8; j++) acc[i][j] += a[i] * b[j];
        }
        __syncthreads();
    }
#pragma unroll
    for (int i = 0; i < 4; i++) {
        float p = 0.f;
#pragma unroll
        for (int j = 0; j < 8; j++) {
            int col = bn + tx * 8 + j;
            p += fmaxf(acc[i][j] + bs2[col], 0.f) * Ws3[col];
        }
        rsm[ty * 4 + i][tx] = p;
    }
    __syncthreads();
    if (tid < 64) {
        float s = 0.f;
#pragma unroll
        for (int j = 0; j < 16; j++) s += rsm[tid][j];
        g_rpart[blockIdx.x][bm + tid] = s;
    }
}

__global__ void rescue_fin_kernel(const float* __restrict__ bs3, float* __restrict__ out_scores) {
    const int i = blockIdx.x * 256 + threadIdx.x;
    const int Nc = min(g_ccount[0], MAXC);
    if (i >= Nc) return;
    float e = bs3[0];
#pragma unroll
    for (int b = 0; b < 8; b++) e += g_rpart[b][i];
    g_cexact[i] = e;
    out_scores[g_cidx[i]] = e;
}

// ---------------- exact top-k among rescued candidates ----------------
__global__ void cand_rank_kernel(float* __restrict__ out_idx) {
    __shared__ float shs[MAXC];
    __shared__ int shi[MAXC];
    const int Nc = min(g_ccount[0], MAXC);
    for (unsigned j = threadIdx.x; j < (unsigned)Nc; j += 1024) {
        shs[j] = g_cexact[j];
        shi[j] = g_cidx[j];
    }
    __syncthreads();
    for (int ib = 0; ib < Nc; ib += 1024) {
        const int i = ib + (int)threadIdx.x;
        if (i >= Nc) break;
        const float my = shs[i];
        const int myi = shi[i];
        int rank = 0;
        for (int j = 0; j < Nc; j++) {
            float v = shs[j];
            rank += (v > my) || (v == my && shi[j] < myi);
        }
        if (rank < KPRUNE) out_idx[rank] = (float)myi;
    }
}

// ---------------- launch ----------------
static void* sym_addr(const void* symbol) {
    void* p = nullptr;
    cudaGetSymbolAddress(&p, symbol);
    return p;
}

extern "C" void kernel_launch(void* const* d_in, const int* in_sizes, int n_in,
                              void* d_out, int out_size) {
    const float* L    = (const float*)d_in[0];
    const float* emb  = (const float*)d_in[1];
    const float* Wa1  = (const float*)d_in[2];
    const float* ba1  = (const float*)d_in[3];
    const float* Wa2  = (const float*)d_in[4];
    const float* ba2  = (const float*)d_in[5];
    const float* Wa3  = (const float*)d_in[6];
    const float* ba3  = (const float*)d_in[7];
    const float* Ws1  = (const float*)d_in[8];
    const float* bs1  = (const float*)d_in[9];
    const float* Ws2  = (const float*)d_in[10];
    const float* bs2  = (const float*)d_in[11];
    const float* Ws3  = (const float*)d_in[12];
    const float* bs3  = (const float*)d_in[13];
    const int* starts = (const int*)d_in[14];
    const int* ends   = (const int*)d_in[15];

    float* out        = (float*)d_out;
    float* out_scores = out;
    float* out_g      = out + SS;
    float* out_idx    = out + SS + (size_t)SS * 3072;

    bf16* Lh  = (bf16*)sym_addr(g_Lh);  bf16* Lm  = (bf16*)sym_addr(g_Lm);
    bf16* WBh = (bf16*)sym_addr(g_WBh); bf16* WBm = (bf16*)sym_addr(g_WBm);
    bf16* pfh = (bf16*)sym_addr(g_pfh); bf16* pfm = (bf16*)sym_addr(g_pfm);
    bf16* s1h = (bf16*)sym_addr(g_s1h); bf16* s1m = (bf16*)sym_addr(g_s1m);
    float* h1  = (float*)sym_addr(g_h1);
    float* h2  = (float*)sym_addr(g_h2);
    float* alp = (float*)sym_addr(g_alpha);
    float* wtd = (float*)sym_addr(g_wtd);
    float* pfx = (float*)sym_addr(g_prefix);
    float* cs  = (float*)sym_addr(g_csum);
    float* PaPb = (float*)sym_addr(g_PaPb);
    float* Q   = (float*)sym_addr(g_Q);
    float* zbias = (float*)sym_addr(g_zbias);

    cudaFuncSetAttribute(mmT3_kernel<0>, cudaFuncAttributeMaxDynamicSharedMemorySize, MM_SMEM2);
    cudaFuncSetAttribute(mmT3_kernel<2>, cudaFuncAttributeMaxDynamicSharedMemorySize, MM_SMEM2);

    const size_t WSZ = (size_t)DD * DD;

    // 1: h1 = relu(L @ Wa1 + ba1)   [fp32 FFMA]
    sgemm_kernel<1><<<dim3(8, 16), 256>>>(L, Wa1, ba1, h1, T_TOK, DD, DD);
    // 2: split L
    split2_kernel<<<T_TOK * DD / 2 / 256, 256>>>(L, Lh, Lm, T_TOK * DD / 2);
    // 3,4: transpose+split Ws1a, Ws1b -> WB rows [0,2048)
    transpose_split2_kernel<<<dim3(32, 32), dim3(32, 8)>>>(Ws1, WBh, WBm);
    transpose_split2_kernel<<<dim3(32, 32), dim3(32, 8)>>>(Ws1 + WSZ, WBh + WSZ, WBm + WSZ);
    // 5: h2 = relu(h1 @ Wa2 + ba2)
    sgemm_kernel<1><<<dim3(8, 16), 256>>>(h1, Wa2, ba2, h2, T_TOK, DD, DD);
    // 6: [Pa|Pb] = L @ [Ws1a|Ws1b]^T   [bf16 T3]  <- ncu target
    mmT3_kernel<0><<<dim3(8, 16), 256, MM_SMEM2>>>(Lh, Lm, WBh, WBm,
                                                   zbias, PaPb, 2048, zbias);
    // 7,8: transpose+split Ws1c -> rows [2048,3072), Ws2 -> rows [3072,4096)
    transpose_split2_kernel<<<dim3(32, 32), dim3(32, 8)>>>(Ws1 + 2 * WSZ, WBh + 2 * WSZ, WBm + 2 * WSZ);
    transpose_split2_kernel<<<dim3(32, 32), dim3(32, 8)>>>(Ws2, WBh + 3 * WSZ, WBm + 3 * WSZ);
    // 9: alpha = h2 @ Wa3 + ba3
    sgemm_kernel<0><<<dim3(8, 16), 256>>>(h2, Wa3, ba3, alp, T_TOK, DD, DD);
    // 10: softmax * embeds
    softmax_mul_kernel<<<T_TOK, 256>>>(alp, emb, wtd);
    // 11-13: prefix scan (+ split planes)
    scan_chunks_kernel<<<dim3(16, 8), 128>>>(wtd, cs);
    scan_offsets_kernel<<<4, 256>>>(cs);
    scan_write2_kernel<<<dim3(16, 8), 128>>>(wtd, cs, pfx, pfh, pfm);
    // 14: Q = prefix @ Ws1c^T
    mmT3_kernel<0><<<dim3(4, 17), 256, MM_SMEM2>>>(pfh, pfm, WBh + 2 * WSZ, WBm + 2 * WSZ,
                                                   zbias, Q, 1024, zbias);
    // 15: g + approx s1 planes
    assemble_kernel<<<SS, 256>>>(L, starts, ends, bs1, out_g);
    // 16: approx scores (fused s2)
    mmT3_kernel<2><<<dim3(4, 160), 256, MM_SMEM2>>>(s1h, s1m, WBh + 3 * WSZ, WBm + 3 * WSZ,
                                                    bs2, nullptr, 0, Ws3);
    // 17: reduce approx scores
    scores_reduce_kernel<<<SS / 256, 256>>>(bs3, out_scores);
    // 18-21: candidate selection
    hist_zero_kernel<<<256, 256>>>();
    hist_build_kernel<<<SS / 256, 256>>>(out_scores);
    hist_cut_kernel<<<1, 1024>>>();
    cand_build_kernel<<<SS / 256, 256>>>(out_scores);
    // 22-24: exact fp32 rescue
    rescue1_kernel<<<dim3(8, 64), 256>>>(out_g, Ws1, bs1);
    rescue2_kernel<<<dim3(8, 64), 256>>>(Ws2, bs2, Ws3);
    rescue_fin_kernel<<<MAXC / 256, 256>>>(bs3, out_scores);
    // 25: exact ranks
    cand_rank_kernel<<<1, 1024>>>(out_idx);
}